// round 5
// baseline (speedup 1.0000x reference)
#include <cuda_runtime.h>
#include <cuda_fp16.h>
#include <cstdint>
#include <math.h>

// ---------------- problem constants ----------------
#define B_ROWS 65536
#define D_IN   512
#define D_H    512
#define D_OUT  128
#define N_EXP  16
#define TILE_M 128
#define MAXP   (B_ROWS + N_EXP * TILE_M)   // 67584
#define MT1    (MAXP / TILE_M)             // 528

// smem geometry
#define A_PADF 40                           // floats per A stage row (160 B, conflict-free)
#define B_PADH 40                           // halves per B stage row (80 B)
#define AST    (128 * A_PADF * 4)           // 20480 B per A stage
#define BST    (128 * B_PADH * 2)           // 10240 B per B stage
#define NST    4
#define OFF_B   (NST * AST)                 // 81920
#define OFF_WET (OFF_B + NST * BST)         // 122880 (128 x 272B rows)
#define OFF_H   (OFF_WET + 128 * 272)       // 157696 (128 x 272B rows)
#define DSM_TOTAL (OFF_H + 128 * 272)       // 192512

// ---------------- device scratch ----------------
__device__ __half g_w1t[(size_t)D_H * D_IN];            // W1^T [n][k], fp16
__device__ __half g_wet[(size_t)N_EXP * D_OUT * D_H];   // We^T [e][o][k], fp16
__device__ int   g_counts[N_EXP];
__device__ int   g_cursor[N_EXP];
__device__ int   g_sorted[MAXP];

// ---------------- helpers ----------------
__device__ __forceinline__ uint32_t smem_u32(const void* p) {
    uint32_t a;
    asm("{ .reg .u64 t; cvta.to.shared.u64 t, %1; cvt.u32.u64 %0, t; }" : "=r"(a) : "l"(p));
    return a;
}
__device__ __forceinline__ void cp16(uint32_t dst, const void* src) {
    asm volatile("cp.async.cg.shared.global [%0], [%1], 16;" :: "r"(dst), "l"(src));
}
#define CP_COMMIT()  asm volatile("cp.async.commit_group;")
#define CP_WAIT_2()  asm volatile("cp.async.wait_group 2;")

__device__ __forceinline__ void mma16(float* c, const uint32_t* a, const uint32_t* b) {
    asm volatile(
        "mma.sync.aligned.m16n8k16.row.col.f32.f16.f16.f32 "
        "{%0,%1,%2,%3}, {%4,%5,%6,%7}, {%8,%9}, {%0,%1,%2,%3};"
        : "+f"(c[0]), "+f"(c[1]), "+f"(c[2]), "+f"(c[3])
        : "r"(a[0]), "r"(a[1]), "r"(a[2]), "r"(a[3]), "r"(b[0]), "r"(b[1]));
}
__device__ __forceinline__ uint32_t f2h2(float2 f) {
    __half2 h = __floats2half2_rn(f.x, f.y);
    return *(uint32_t*)&h;
}

// ---------------- routing ----------------
__global__ void r1_count(const int* __restrict__ num, const int* __restrict__ c) {
    __shared__ int h[N_EXP];
    int tid = threadIdx.x;
    if (tid < N_EXP) h[tid] = 0;
    __syncthreads();
    int i = blockIdx.x * blockDim.x + tid;
    if (i < B_ROWS) atomicAdd(&h[c[num[i]]], 1);
    __syncthreads();
    if (tid < N_EXP && h[tid]) atomicAdd(&g_counts[tid], h[tid]);
}
__global__ void r3_scatter(const int* __restrict__ num, const int* __restrict__ c) {
    __shared__ int sstart[N_EXP];
    int tid = threadIdx.x;
    if (tid < N_EXP) {                     // inline 16-entry padded scan
        int s = 0;
        for (int e2 = 0; e2 < tid; e2++) s += (g_counts[e2] + TILE_M - 1) & ~(TILE_M - 1);
        sstart[tid] = s;
    }
    __syncthreads();
    int i = blockIdx.x * blockDim.x + tid;
    if (i >= B_ROWS) return;
    int e = c[num[i]];
    unsigned lane = tid & 31;
    unsigned mask = __match_any_sync(0xffffffffu, e);
    int leader = __ffs(mask) - 1;
    int rank = __popc(mask & ((1u << lane) - 1u));
    int base = 0;
    if ((int)lane == leader) base = atomicAdd(&g_cursor[e], __popc(mask));
    base = __shfl_sync(0xffffffffu, base, leader);
    g_sorted[sstart[e] + base + rank] = i;
}

// ---------------- weight transposes (fp16); tr_w1 also zeroes counters ----------------
__global__ void tr_w1(const float* __restrict__ W1) {
    if (blockIdx.x == 0 && blockIdx.y == 0 && threadIdx.y == 0 && threadIdx.x < N_EXP) {
        g_counts[threadIdx.x] = 0;
        g_cursor[threadIdx.x] = 0;
    }
    __shared__ float t[32][33];
    int x0 = blockIdx.x * 32;   // n
    int y0 = blockIdx.y * 32;   // k
    for (int i = threadIdx.y; i < 32; i += 8)
        t[i][threadIdx.x] = W1[(size_t)(y0 + i) * D_H + x0 + threadIdx.x];
    __syncthreads();
    for (int i = threadIdx.y; i < 32; i += 8)
        g_w1t[(size_t)(x0 + i) * D_IN + y0 + threadIdx.x] = __float2half_rn(t[threadIdx.x][i]);
}
__global__ void tr_we(const float* __restrict__ We) {
    __shared__ float t[32][33];
    int e = blockIdx.z;
    int x0 = blockIdx.x * 32;   // o
    int y0 = blockIdx.y * 32;   // k
    const float* src = We + (size_t)e * D_H * D_OUT;
    for (int i = threadIdx.y; i < 32; i += 8)
        t[i][threadIdx.x] = src[(size_t)(y0 + i) * D_OUT + x0 + threadIdx.x];
    __syncthreads();
    __half* dst = g_wet + (size_t)e * D_OUT * D_H;
    for (int i = threadIdx.y; i < 32; i += 8)
        dst[(size_t)(x0 + i) * D_H + y0 + threadIdx.x] = __float2half_rn(t[threadIdx.x][i]);
}

// ================= fused megakernel =================
// per 128-row tile: for bn=0..3 { h_blk = relu(x@W1T[bn]+b1) -> smem;
//                                 acc2 += h_blk @ WeT[e][:,bn] }  -> sigmoid -> scatter
__global__ __launch_bounds__(256) void fused(const float* __restrict__ x,
                                             const float* __restrict__ b1,
                                             const float* __restrict__ be,
                                             float* __restrict__ out) {
    __shared__ int   rows_s[128];
    __shared__ float bias1[512];
    __shared__ float bias2[128];
    __shared__ int   sstart[N_EXP + 1];
    extern __shared__ char dsm[];

    const int tid = threadIdx.x, lane = tid & 31, wid = tid >> 5;

    if (tid <= N_EXP) {                     // inline padded scan
        int s = 0;
        for (int e2 = 0; e2 < tid; e2++) s += (g_counts[e2] + TILE_M - 1) & ~(TILE_M - 1);
        sstart[tid] = s;
    }
    __syncthreads();

    const int p0 = blockIdx.x * TILE_M;
    if (p0 >= sstart[N_EXP]) return;        // padding-only region: uniform exit

    int e = 0;
    while (e < N_EXP - 1 && sstart[e + 1] <= p0) e++;
    const int valid_end = sstart[e] + g_counts[e];

    if (tid < 128) {
        int r = g_sorted[p0 + tid];
        rows_s[tid] = min(max(r, 0), B_ROWS - 1);
        bias2[tid] = be[e * D_OUT + tid];
    }
    for (int i = tid; i < 512; i += 256) bias1[i] = b1[i];
    __syncthreads();

    const uint32_t sbA = smem_u32(dsm);
    const uint32_t sbB = sbA + OFF_B;
    const uint32_t sbW = sbA + OFF_WET;
    const uint32_t sbH = sbA + OFF_H;

    // A chunk map: 1024 x 16B chunks (128 rows x 32 fp32) -> 4/thread
    const float* asrc[4];
    uint32_t adst[4];
#pragma unroll
    for (int i = 0; i < 4; i++) {
        int id = tid + i * 256;
        int r = id >> 3, q = id & 7;
        asrc[i] = x + (size_t)rows_s[r] * D_IN + q * 4;
        adst[i] = sbA + (uint32_t)(r * (A_PADF * 4) + q * 16);
    }
    // B chunk map: 512 chunks (128 rows x 32 fp16) -> 2/thread
    int b_r[2], b_q[2];
    uint32_t bdst[2];
#pragma unroll
    for (int i = 0; i < 2; i++) {
        int id = tid + i * 256;
        b_r[i] = id >> 2; b_q[i] = id & 3;
        bdst[i] = sbB + (uint32_t)(b_r[i] * (B_PADH * 2) + b_q[i] * 16);
    }

    const int wm = wid >> 2, wn = wid & 3;
    const int lr = lane >> 2, lc = lane & 3;

    float acc2[4][4][4];
#pragma unroll
    for (int mt = 0; mt < 4; mt++)
#pragma unroll
        for (int nt = 0; nt < 4; nt++)
#pragma unroll
            for (int k = 0; k < 4; k++) acc2[mt][nt][k] = 0.f;

    const __half* wet_e = g_wet + (size_t)e * D_OUT * D_H;

    for (int bn = 0; bn < 4; bn++) {
        const __half* bsrc[2];
#pragma unroll
        for (int i = 0; i < 2; i++)
            bsrc[i] = g_w1t + (size_t)(bn * 128 + b_r[i]) * D_IN + b_q[i] * 8;

        // prefetch group 0: WeT block (2048 chunks, 8/thread) + stage 0
        {
            const __half* ws = wet_e + bn * 128;
#pragma unroll
            for (int i = 0; i < 8; i++) {
                int id = tid + i * 256;
                int r = id >> 4, q = id & 15;
                cp16(sbW + (uint32_t)(r * 272 + q * 16), ws + (size_t)r * D_H + q * 8);
            }
#pragma unroll
            for (int i = 0; i < 4; i++) cp16(adst[i], asrc[i]);
#pragma unroll
            for (int i = 0; i < 2; i++) cp16(bdst[i], bsrc[i]);
            CP_COMMIT();
        }
        // prefetch stages 1,2
#pragma unroll
        for (int s = 1; s <= 2; s++) {
            uint32_t ao = (uint32_t)(s * AST), bo = (uint32_t)(s * BST);
#pragma unroll
            for (int i = 0; i < 4; i++) cp16(adst[i] + ao, asrc[i] + s * 32);
#pragma unroll
            for (int i = 0; i < 2; i++) cp16(bdst[i] + bo, bsrc[i] + s * 32);
            CP_COMMIT();
        }

        float acc1[4][4][4];
#pragma unroll
        for (int mt = 0; mt < 4; mt++)
#pragma unroll
            for (int nt = 0; nt < 4; nt++)
#pragma unroll
                for (int k = 0; k < 4; k++) acc1[mt][nt][k] = 0.f;

        // ---- GEMM1 mainloop: K=512, 16 stages of 32 ----
        for (int s = 0; s < 16; s++) {
            CP_WAIT_2();
            __syncthreads();
            if (s + 3 < 16) {
                uint32_t ao = (uint32_t)(((s + 3) & (NST - 1)) * AST);
                uint32_t bo = (uint32_t)(((s + 3) & (NST - 1)) * BST);
                int k = (s + 3) * 32;
#pragma unroll
                for (int i = 0; i < 4; i++) cp16(adst[i] + ao, asrc[i] + k);
#pragma unroll
                for (int i = 0; i < 2; i++) cp16(bdst[i] + bo, bsrc[i] + k);
            }
            CP_COMMIT();

            const float*    Af = (const float*)(dsm + (s & (NST - 1)) * AST);
            const uint32_t* Bh = (const uint32_t*)(dsm + OFF_B + (s & (NST - 1)) * BST);
#pragma unroll
            for (int ks = 0; ks < 2; ks++) {
                const int kf = ks * 16;      // float offset in A row
                const int kq = ks * 8;       // uint32 offset in B row
                uint32_t a[4][4], b[4][2];
#pragma unroll
                for (int mt = 0; mt < 4; mt++) {
                    int row = wm * 64 + mt * 16 + lr;
                    float2 f0 = *(const float2*)(Af + row * A_PADF + kf + 2 * lc);
                    float2 f1 = *(const float2*)(Af + (row + 8) * A_PADF + kf + 2 * lc);
                    float2 f2 = *(const float2*)(Af + row * A_PADF + kf + 2 * lc + 8);
                    float2 f3 = *(const float2*)(Af + (row + 8) * A_PADF + kf + 2 * lc + 8);
                    a[mt][0] = f2h2(f0); a[mt][1] = f2h2(f1);
                    a[mt][2] = f2h2(f2); a[mt][3] = f2h2(f3);
                }
#pragma unroll
                for (int nt = 0; nt < 4; nt++) {
                    int col = wn * 32 + nt * 8 + lr;
                    b[nt][0] = Bh[col * (B_PADH / 2) + kq + lc];
                    b[nt][1] = Bh[col * (B_PADH / 2) + kq + lc + 4];
                }
#pragma unroll
                for (int mt = 0; mt < 4; mt++)
#pragma unroll
                    for (int nt = 0; nt < 4; nt++)
                        mma16(acc1[mt][nt], a[mt], b[nt]);
            }
        }
        __syncthreads();   // stage-buffer reads done (also orders vs prev gemm2's h reads)

        // ---- epilogue 1: h_blk = relu(acc1 + b1) as fp16 -> smem ----
#pragma unroll
        for (int mt = 0; mt < 4; mt++) {
            int m = wm * 64 + mt * 16 + lr;
#pragma unroll
            for (int nt = 0; nt < 4; nt++) {
                int n = wn * 32 + nt * 8 + lc * 2;
                float bi0 = bias1[bn * 128 + n], bi1 = bias1[bn * 128 + n + 1];
                __half2 v0 = __floats2half2_rn(fmaxf(acc1[mt][nt][0] + bi0, 0.f),
                                               fmaxf(acc1[mt][nt][1] + bi1, 0.f));
                __half2 v1 = __floats2half2_rn(fmaxf(acc1[mt][nt][2] + bi0, 0.f),
                                               fmaxf(acc1[mt][nt][3] + bi1, 0.f));
                *(uint32_t*)(dsm + OFF_H + m * 272 + n * 2)       = *(uint32_t*)&v0;
                *(uint32_t*)(dsm + OFF_H + (m + 8) * 272 + n * 2) = *(uint32_t*)&v1;
            }
        }
        __syncthreads();

        // ---- GEMM2 partial: acc2 += h_blk(128x128) @ WeT_blk(128x128) ----
        {
            const uint32_t* Ah = (const uint32_t*)(dsm + OFF_H);
            const uint32_t* Bw = (const uint32_t*)(dsm + OFF_WET);
#pragma unroll
            for (int ks = 0; ks < 8; ks++) {
                const int kq = ks * 8;
                uint32_t a[4][4], b[4][2];
#pragma unroll
                for (int mt = 0; mt < 4; mt++) {
                    int row = wm * 64 + mt * 16 + lr;
                    a[mt][0] = Ah[row * 68 + kq + lc];
                    a[mt][1] = Ah[(row + 8) * 68 + kq + lc];
                    a[mt][2] = Ah[row * 68 + kq + lc + 4];
                    a[mt][3] = Ah[(row + 8) * 68 + kq + lc + 4];
                }
#pragma unroll
                for (int nt = 0; nt < 4; nt++) {
                    int col = wn * 32 + nt * 8 + lr;
                    b[nt][0] = Bw[col * 68 + kq + lc];
                    b[nt][1] = Bw[col * 68 + kq + lc + 4];
                }
#pragma unroll
                for (int mt = 0; mt < 4; mt++)
#pragma unroll
                    for (int nt = 0; nt < 4; nt++)
                        mma16(acc2[mt][nt], a[mt], b[nt]);
            }
        }
        __syncthreads();   // h_blk/wet reads done before next bn overwrites
    }

    // ---- final epilogue: sigmoid(acc2 + be) scatter to original rows ----
#pragma unroll
    for (int mt = 0; mt < 4; mt++) {
        int m = wm * 64 + mt * 16 + lr;
#pragma unroll
        for (int nt = 0; nt < 4; nt++) {
            int n = wn * 32 + nt * 8 + lc * 2;
            float bi0 = bias2[n], bi1 = bias2[n + 1];
            if (p0 + m < valid_end) {
                float2 v;
                v.x = 1.f / (1.f + __expf(-(acc2[mt][nt][0] + bi0)));
                v.y = 1.f / (1.f + __expf(-(acc2[mt][nt][1] + bi1)));
                *(float2*)(out + (size_t)rows_s[m] * D_OUT + n) = v;
            }
            if (p0 + m + 8 < valid_end) {
                float2 v;
                v.x = 1.f / (1.f + __expf(-(acc2[mt][nt][2] + bi0)));
                v.y = 1.f / (1.f + __expf(-(acc2[mt][nt][3] + bi1)));
                *(float2*)(out + (size_t)rows_s[m + 8] * D_OUT + n) = v;
            }
        }
    }
}

// ---------------- launch ----------------
extern "C" void kernel_launch(void* const* d_in, const int* in_sizes, int n_in,
                              void* d_out, int out_size) {
    const float* x   = (const float*)d_in[0];
    const int*   num = (const int*)d_in[1];
    const int*   c   = (const int*)d_in[2];
    const float* W1  = (const float*)d_in[3];
    const float* b1  = (const float*)d_in[4];
    const float* We  = (const float*)d_in[5];
    const float* be  = (const float*)d_in[6];
    float* out = (float*)d_out;

    static bool attr_done = false;
    if (!attr_done) {
        cudaFuncSetAttribute(fused, cudaFuncAttributeMaxDynamicSharedMemorySize, DSM_TOTAL);
        attr_done = true;
    }

    dim3 tb(32, 8);
    tr_w1<<<dim3(16, 16), tb>>>(W1);      // also zeroes routing counters
    tr_we<<<dim3(4, 16, 16), tb>>>(We);

    r1_count<<<B_ROWS / 256, 256>>>(num, c);
    r3_scatter<<<B_ROWS / 256, 256>>>(num, c);

    fused<<<MT1, 256, DSM_TOTAL>>>(x, b1, be, out);
}

// round 6
// speedup vs baseline: 1.2236x; 1.2236x over previous
#include <cuda_runtime.h>
#include <cuda_fp16.h>
#include <cstdint>
#include <math.h>

// ---------------- problem constants ----------------
#define B_ROWS 65536
#define D_IN   512
#define D_H    512
#define D_OUT  128
#define N_EXP  16
#define TILE_M 128
#define MAXP   (B_ROWS + N_EXP * TILE_M)   // 67584
#define MT1    (MAXP / TILE_M)             // 528

// ---- gemm1 smem geometry: A fp32 + B fp16, 3 stages ----
#define A_PADF 40                           // floats per A row (160 B)
#define B_PADH 40                           // halves per B row (80 B)
#define G1_AST (128 * A_PADF * 4)           // 20480
#define G1_BST (128 * B_PADH * 2)           // 10240
#define G1_STG (G1_AST + G1_BST)            // 30720
#define G1_NST 3
#define G1_SMEM (G1_NST * G1_STG)           // 92160  -> 2 CTAs/SM

// ---- gemm2 smem geometry: both fp16, 4 stages (round-4 proven) ----
#define G2_ST  (128 * B_PADH * 2)           // 10240 per operand
#define G2_STG (2 * G2_ST)                  // 20480
#define G2_NST 4
#define G2_SMEM (G2_NST * G2_STG)           // 81920  -> 2 CTAs/SM

// ---------------- device scratch ----------------
__device__ __half g_h[(size_t)MAXP * D_H];              // sorted hidden acts, fp16
__device__ __half g_w1t[(size_t)D_H * D_IN];            // W1^T [n][k], fp16
__device__ __half g_wet[(size_t)N_EXP * D_OUT * D_H];   // We^T [e][o][k], fp16
__device__ int   g_counts[N_EXP];
__device__ int   g_cursor[N_EXP];
__device__ int   g_sorted[MAXP];

// ---------------- helpers ----------------
__device__ __forceinline__ uint32_t smem_u32(const void* p) {
    uint32_t a;
    asm("{ .reg .u64 t; cvta.to.shared.u64 t, %1; cvt.u32.u64 %0, t; }" : "=r"(a) : "l"(p));
    return a;
}
__device__ __forceinline__ void cp16(uint32_t dst, const void* src) {
    asm volatile("cp.async.cg.shared.global [%0], [%1], 16;" :: "r"(dst), "l"(src));
}
#define CP_COMMIT()  asm volatile("cp.async.commit_group;")
#define CP_WAIT_1()  asm volatile("cp.async.wait_group 1;")
#define CP_WAIT_2()  asm volatile("cp.async.wait_group 2;")

__device__ __forceinline__ void mma16(float* c, const uint32_t* a, const uint32_t* b) {
    asm volatile(
        "mma.sync.aligned.m16n8k16.row.col.f32.f16.f16.f32 "
        "{%0,%1,%2,%3}, {%4,%5,%6,%7}, {%8,%9}, {%0,%1,%2,%3};"
        : "+f"(c[0]), "+f"(c[1]), "+f"(c[2]), "+f"(c[3])
        : "r"(a[0]), "r"(a[1]), "r"(a[2]), "r"(a[3]), "r"(b[0]), "r"(b[1]));
}
__device__ __forceinline__ uint32_t f2h2(float2 f) {
    __half2 h = __floats2half2_rn(f.x, f.y);
    return *(uint32_t*)&h;
}

// ---------------- routing ----------------
__global__ void r1_count(const int* __restrict__ num, const int* __restrict__ c) {
    __shared__ int h[N_EXP];
    int tid = threadIdx.x;
    if (tid < N_EXP) h[tid] = 0;
    __syncthreads();
    int i = blockIdx.x * blockDim.x + tid;
    if (i < B_ROWS) atomicAdd(&h[c[num[i]]], 1);
    __syncthreads();
    if (tid < N_EXP && h[tid]) atomicAdd(&g_counts[tid], h[tid]);
}
__global__ void r3_scatter(const int* __restrict__ num, const int* __restrict__ c) {
    __shared__ int sstart[N_EXP];
    int tid = threadIdx.x;
    if (tid < N_EXP) {                     // inline 16-entry padded scan
        int s = 0;
        for (int e2 = 0; e2 < tid; e2++) s += (g_counts[e2] + TILE_M - 1) & ~(TILE_M - 1);
        sstart[tid] = s;
    }
    __syncthreads();
    int i = blockIdx.x * blockDim.x + tid;
    if (i >= B_ROWS) return;
    int e = c[num[i]];
    unsigned lane = tid & 31;
    unsigned mask = __match_any_sync(0xffffffffu, e);
    int leader = __ffs(mask) - 1;
    int rank = __popc(mask & ((1u << lane) - 1u));
    int base = 0;
    if ((int)lane == leader) base = atomicAdd(&g_cursor[e], __popc(mask));
    base = __shfl_sync(0xffffffffu, base, leader);
    g_sorted[sstart[e] + base + rank] = i;
}

// ---------------- weight transposes (fp16); tr_w1 also zeroes counters ----------------
__global__ void tr_w1(const float* __restrict__ W1) {
    if (blockIdx.x == 0 && blockIdx.y == 0 && threadIdx.y == 0 && threadIdx.x < N_EXP) {
        g_counts[threadIdx.x] = 0;
        g_cursor[threadIdx.x] = 0;
    }
    __shared__ float t[32][33];
    int x0 = blockIdx.x * 32;   // n
    int y0 = blockIdx.y * 32;   // k
    for (int i = threadIdx.y; i < 32; i += 8)
        t[i][threadIdx.x] = W1[(size_t)(y0 + i) * D_H + x0 + threadIdx.x];
    __syncthreads();
    for (int i = threadIdx.y; i < 32; i += 8)
        g_w1t[(size_t)(x0 + i) * D_IN + y0 + threadIdx.x] = __float2half_rn(t[threadIdx.x][i]);
}
__global__ void tr_we(const float* __restrict__ We) {
    __shared__ float t[32][33];
    int e = blockIdx.z;
    int x0 = blockIdx.x * 32;   // o
    int y0 = blockIdx.y * 32;   // k
    const float* src = We + (size_t)e * D_H * D_OUT;
    for (int i = threadIdx.y; i < 32; i += 8)
        t[i][threadIdx.x] = src[(size_t)(y0 + i) * D_OUT + x0 + threadIdx.x];
    __syncthreads();
    __half* dst = g_wet + (size_t)e * D_OUT * D_H;
    for (int i = threadIdx.y; i < 32; i += 8)
        dst[(size_t)(x0 + i) * D_H + y0 + threadIdx.x] = __float2half_rn(t[threadIdx.x][i]);
}

// ---------------- GEMM1: h = relu(x[sorted] @ W1 + b1) ----------------
// x read as fp32, converted to fp16 post-LDS; 3-stage cp.async; 2 CTAs/SM
__global__ __launch_bounds__(256, 2) void gemm1(const float* __restrict__ x,
                                                const float* __restrict__ b1) {
    __shared__ int   rows_s[128];
    __shared__ float bias_s[128];
    __shared__ int   s_total;
    extern __shared__ char dsm[];

    const int tid = threadIdx.x, lane = tid & 31, wid = tid >> 5;
    const int bn = blockIdx.x;
    const int p0 = blockIdx.y * TILE_M;

    if (tid == 0) {                        // inline padded total
        int s = 0;
        for (int e2 = 0; e2 < N_EXP; e2++) s += (g_counts[e2] + TILE_M - 1) & ~(TILE_M - 1);
        s_total = s;
    }
    if (tid < 128) {
        int r = g_sorted[p0 + tid];
        rows_s[tid] = min(max(r, 0), B_ROWS - 1);
        bias_s[tid] = b1[bn * 128 + tid];
    }
    __syncthreads();
    if (p0 >= s_total) return;             // padding-only tile

    const uint32_t sb = smem_u32(dsm);

    // A: 128 rows x 32 fp32 = 1024 chunks -> 4/thread ; B: 512 chunks -> 2/thread
    const float* asrc[4];
    uint32_t adst[4];
#pragma unroll
    for (int i = 0; i < 4; i++) {
        int id = tid + i * 256;
        int r = id >> 3, q = id & 7;
        asrc[i] = x + (size_t)rows_s[r] * D_IN + q * 4;
        adst[i] = sb + (uint32_t)(r * (A_PADF * 4) + q * 16);
    }
    const __half* bsrc[2];
    uint32_t bdst[2];
#pragma unroll
    for (int i = 0; i < 2; i++) {
        int id = tid + i * 256;
        int r = id >> 2, q = id & 3;
        bsrc[i] = g_w1t + (size_t)(bn * 128 + r) * D_IN + q * 8;
        bdst[i] = sb + (uint32_t)(G1_AST + r * (B_PADH * 2) + q * 16);
    }

    // prefetch stages 0,1
#pragma unroll
    for (int s = 0; s < 2; s++) {
        uint32_t off = (uint32_t)(s * G1_STG);
        int k = s * 32;
#pragma unroll
        for (int i = 0; i < 4; i++) cp16(adst[i] + off, asrc[i] + k);
#pragma unroll
        for (int i = 0; i < 2; i++) cp16(bdst[i] + off, bsrc[i] + k);
        CP_COMMIT();
    }

    float acc[4][4][4];
#pragma unroll
    for (int mt = 0; mt < 4; mt++)
#pragma unroll
        for (int nt = 0; nt < 4; nt++)
#pragma unroll
            for (int k = 0; k < 4; k++) acc[mt][nt][k] = 0.f;

    const int wm = wid >> 2, wn = wid & 3;
    const int lr = lane >> 2, lc = lane & 3;

    for (int s = 0; s < 16; s++) {
        CP_WAIT_1();
        __syncthreads();
        if (s + 2 < 16) {
            uint32_t off = (uint32_t)(((s + 2) % G1_NST) * G1_STG);
            int k = (s + 2) * 32;
#pragma unroll
            for (int i = 0; i < 4; i++) cp16(adst[i] + off, asrc[i] + k);
#pragma unroll
            for (int i = 0; i < 2; i++) cp16(bdst[i] + off, bsrc[i] + k);
        }
        CP_COMMIT();

        const float*    Af = (const float*)(dsm + (s % G1_NST) * G1_STG);
        const uint32_t* Bh = (const uint32_t*)(dsm + (s % G1_NST) * G1_STG + G1_AST);
#pragma unroll
        for (int ks = 0; ks < 2; ks++) {
            const int kf = ks * 16;      // float offset in A row
            const int kq = ks * 8;       // uint32 offset in B row
            uint32_t a[4][4], b[4][2];
#pragma unroll
            for (int mt = 0; mt < 4; mt++) {
                int row = wm * 64 + mt * 16 + lr;
                float2 f0 = *(const float2*)(Af + row * A_PADF + kf + 2 * lc);
                float2 f1 = *(const float2*)(Af + (row + 8) * A_PADF + kf + 2 * lc);
                float2 f2 = *(const float2*)(Af + row * A_PADF + kf + 2 * lc + 8);
                float2 f3 = *(const float2*)(Af + (row + 8) * A_PADF + kf + 2 * lc + 8);
                a[mt][0] = f2h2(f0); a[mt][1] = f2h2(f1);
                a[mt][2] = f2h2(f2); a[mt][3] = f2h2(f3);
            }
#pragma unroll
            for (int nt = 0; nt < 4; nt++) {
                int col = wn * 32 + nt * 8 + lr;
                b[nt][0] = Bh[col * (B_PADH / 2) + kq + lc];
                b[nt][1] = Bh[col * (B_PADH / 2) + kq + lc + 4];
            }
#pragma unroll
            for (int mt = 0; mt < 4; mt++)
#pragma unroll
                for (int nt = 0; nt < 4; nt++)
                    mma16(acc[mt][nt], a[mt], b[nt]);
        }
    }

    // epilogue: bias + relu, write sorted h as fp16
#pragma unroll
    for (int mt = 0; mt < 4; mt++) {
        int m = wm * 64 + mt * 16 + lr;
#pragma unroll
        for (int nt = 0; nt < 4; nt++) {
            int n = wn * 32 + nt * 8 + lc * 2;
            float bi0 = bias_s[n], bi1 = bias_s[n + 1];
            __half2 v0 = __floats2half2_rn(fmaxf(acc[mt][nt][0] + bi0, 0.f),
                                           fmaxf(acc[mt][nt][1] + bi1, 0.f));
            __half2 v1 = __floats2half2_rn(fmaxf(acc[mt][nt][2] + bi0, 0.f),
                                           fmaxf(acc[mt][nt][3] + bi1, 0.f));
            *(__half2*)(g_h + (size_t)(p0 + m) * D_H + bn * 128 + n) = v0;
            *(__half2*)(g_h + (size_t)(p0 + m + 8) * D_H + bn * 128 + n) = v1;
        }
    }
}

// ---------------- GEMM2: out[orig] = sigmoid(h @ We[e]^T + be[e]) ----------------
__global__ __launch_bounds__(256, 2) void gemm2(const float* __restrict__ be,
                                                float* __restrict__ out) {
    __shared__ int   rows_s[128];
    __shared__ float bias_s[128];
    __shared__ int   sstart[N_EXP + 1];
    extern __shared__ char dsm[];

    const int tid = threadIdx.x, lane = tid & 31, wid = tid >> 5;

    if (tid <= N_EXP) {                    // inline padded scan
        int s = 0;
        for (int e2 = 0; e2 < tid; e2++) s += (g_counts[e2] + TILE_M - 1) & ~(TILE_M - 1);
        sstart[tid] = s;
    }
    __syncthreads();

    const int p0 = blockIdx.x * TILE_M;
    if (p0 >= sstart[N_EXP]) return;

    int e = 0;
    while (e < N_EXP - 1 && sstart[e + 1] <= p0) e++;
    const int valid_end = sstart[e] + g_counts[e];

    if (tid < 128) {
        rows_s[tid] = g_sorted[p0 + tid];
        bias_s[tid] = be[e * D_OUT + tid];
    }
    __syncthreads();

    const uint32_t sb = smem_u32(dsm);
    const __half* Ab = g_h + (size_t)p0 * D_H;
    const __half* Bb = g_wet + (size_t)e * D_OUT * D_H;

    const __half* asrc[2];
    const __half* bsrc[2];
    uint32_t adst[2], bdst[2];
#pragma unroll
    for (int i = 0; i < 2; i++) {
        int id = tid + i * 256;
        int r = id >> 2, q = id & 3;
        asrc[i] = Ab + (size_t)r * D_H + q * 8;
        bsrc[i] = Bb + (size_t)r * D_H + q * 8;
        adst[i] = sb + (uint32_t)(r * (B_PADH * 2) + q * 16);
        bdst[i] = adst[i] + G2_ST;
    }

#pragma unroll
    for (int s = 0; s < 3; s++) {
        uint32_t off = (uint32_t)(s * G2_STG);
        int k = s * 32;
#pragma unroll
        for (int i = 0; i < 2; i++) {
            cp16(adst[i] + off, asrc[i] + k);
            cp16(bdst[i] + off, bsrc[i] + k);
        }
        CP_COMMIT();
    }

    float acc[4][4][4];
#pragma unroll
    for (int mt = 0; mt < 4; mt++)
#pragma unroll
        for (int nt = 0; nt < 4; nt++)
#pragma unroll
            for (int k = 0; k < 4; k++) acc[mt][nt][k] = 0.f;

    const int wm = wid >> 2, wn = wid & 3;
    const int lr = lane >> 2, lc = lane & 3;

    for (int s = 0; s < 16; s++) {
        CP_WAIT_2();
        __syncthreads();
        if (s + 3 < 16) {
            uint32_t off = (uint32_t)(((s + 3) & (G2_NST - 1)) * G2_STG);
            int k = (s + 3) * 32;
#pragma unroll
            for (int i = 0; i < 2; i++) {
                cp16(adst[i] + off, asrc[i] + k);
                cp16(bdst[i] + off, bsrc[i] + k);
            }
        }
        CP_COMMIT();

        const uint32_t* As = (const uint32_t*)(dsm + (s & (G2_NST - 1)) * G2_STG);
        const uint32_t* Bs = (const uint32_t*)(dsm + (s & (G2_NST - 1)) * G2_STG + G2_ST);
#pragma unroll
        for (int ks = 0; ks < 2; ks++) {
            const int kq = ks * 8;
            uint32_t a[4][4], b[4][2];
#pragma unroll
            for (int mt = 0; mt < 4; mt++) {
                int row = wm * 64 + mt * 16 + lr;
                a[mt][0] = As[row * (B_PADH / 2) + kq + lc];
                a[mt][1] = As[(row + 8) * (B_PADH / 2) + kq + lc];
                a[mt][2] = As[row * (B_PADH / 2) + kq + lc + 4];
                a[mt][3] = As[(row + 8) * (B_PADH / 2) + kq + lc + 4];
            }
#pragma unroll
            for (int nt = 0; nt < 4; nt++) {
                int col = wn * 32 + nt * 8 + lr;
                b[nt][0] = Bs[col * (B_PADH / 2) + kq + lc];
                b[nt][1] = Bs[col * (B_PADH / 2) + kq + lc + 4];
            }
#pragma unroll
            for (int mt = 0; mt < 4; mt++)
#pragma unroll
                for (int nt = 0; nt < 4; nt++)
                    mma16(acc[mt][nt], a[mt], b[nt]);
        }
    }

    // epilogue: bias + sigmoid, scatter valid rows
#pragma unroll
    for (int mt = 0; mt < 4; mt++) {
        int m = wm * 64 + mt * 16 + lr;
#pragma unroll
        for (int nt = 0; nt < 4; nt++) {
            int n = wn * 32 + nt * 8 + lc * 2;
            float bi0 = bias_s[n], bi1 = bias_s[n + 1];
            if (p0 + m < valid_end) {
                float2 v;
                v.x = 1.f / (1.f + __expf(-(acc[mt][nt][0] + bi0)));
                v.y = 1.f / (1.f + __expf(-(acc[mt][nt][1] + bi1)));
                *(float2*)(out + (size_t)rows_s[m] * D_OUT + n) = v;
            }
            if (p0 + m + 8 < valid_end) {
                float2 v;
                v.x = 1.f / (1.f + __expf(-(acc[mt][nt][2] + bi0)));
                v.y = 1.f / (1.f + __expf(-(acc[mt][nt][3] + bi1)));
                *(float2*)(out + (size_t)rows_s[m + 8] * D_OUT + n) = v;
            }
        }
    }
}

// ---------------- launch ----------------
extern "C" void kernel_launch(void* const* d_in, const int* in_sizes, int n_in,
                              void* d_out, int out_size) {
    const float* x   = (const float*)d_in[0];
    const int*   num = (const int*)d_in[1];
    const int*   c   = (const int*)d_in[2];
    const float* W1  = (const float*)d_in[3];
    const float* b1  = (const float*)d_in[4];
    const float* We  = (const float*)d_in[5];
    const float* be  = (const float*)d_in[6];
    float* out = (float*)d_out;

    static bool attr_done = false;
    if (!attr_done) {
        cudaFuncSetAttribute(gemm1, cudaFuncAttributeMaxDynamicSharedMemorySize, G1_SMEM);
        cudaFuncSetAttribute(gemm2, cudaFuncAttributeMaxDynamicSharedMemorySize, G2_SMEM);
        attr_done = true;
    }

    dim3 tb(32, 8);
    tr_w1<<<dim3(16, 16), tb>>>(W1);      // also zeroes routing counters
    tr_we<<<dim3(4, 16, 16), tb>>>(We);

    r1_count<<<B_ROWS / 256, 256>>>(num, c);
    r3_scatter<<<B_ROWS / 256, 256>>>(num, c);

    gemm1<<<dim3(4, MT1), 256, G1_SMEM>>>(x, b1);
    gemm2<<<MT1, 256, G2_SMEM>>>(be, out);
}